// round 2
// baseline (speedup 1.0000x reference)
#include <cuda_runtime.h>

#define NW      18
#define NBITS   18
#define DIM     (1 << NBITS)
#define BATCH   64
#define TILE    16384          // 2^14 amplitudes staged per CTA (128 KB re+im)
#define THREADS 1024
#define CHUNKS  16             // tiles per batch element (DIM / TILE)
#define NPART   15             // 14 signed bit-sums + total prob

// Scratch state (128 MB) — __device__ globals per allocation rules.
__device__ float  g_re[(size_t)BATCH * DIM];
__device__ float  g_im[(size_t)BATCH * DIM];
__device__ float4 g_trig[3][NW];                       // cy, sy, cz, sz per (layer, wire)
__device__ float  g_part[BATCH * CHUNKS * NPART];      // expval partials

// ---------------------------------------------------------------------------
__global__ void prep_kernel(const float* __restrict__ params) {
    int t = threadIdx.x;
    if (t < 3 * NW) {
        int l = t / NW, w = t % NW;
        float cy, sy, cz, sz;
        sincosf(0.5f * params[l * 36 + w],       &sy, &cy);   // params[l,0,w]
        sincosf(0.5f * params[l * 36 + NW + w],  &sz, &cz);   // params[l,1,w]
        g_trig[l][w] = make_float4(cy, sy, cz, sz);
    }
}

// Fused RY then RZ on an amplitude pair (m0: bit=0, m1: bit=1).
__device__ __forceinline__ void rot_pair(float* sre, float* sim, int m0, int m1,
                                         float cy, float sy, float cz, float sz) {
    float ar = sre[m0], ai = sim[m0], br = sre[m1], bi = sim[m1];
    float nar = cy * ar - sy * br, nai = cy * ai - sy * bi;   // RY
    float nbr = sy * ar + cy * br, nbi = sy * ai + cy * bi;
    sre[m0] = nar * cz + nai * sz;                            // RZ: * exp(-i th/2)
    sim[m0] = nai * cz - nar * sz;
    sre[m1] = nbr * cz - nbi * sz;                            // RZ: * exp(+i th/2)
    sim[m1] = nbi * cz + nbr * sz;
}

// ---------------------------------------------------------------------------
// H pass: bits 9..17 (wires 0..8). Tile = all 512 high combos x 32 contiguous lows.
// SMEM index m = h*32 + lo, global = b*DIM + h*512 + chunk*32 + lo.
__global__ __launch_bounds__(THREADS, 1)
void h_kernel(const float* __restrict__ in_re, const float* __restrict__ in_im, int layer) {
    extern __shared__ float smem[];
    float* sre = smem;
    float* sim = smem + TILE;
    const int    t     = threadIdx.x;
    const int    b     = blockIdx.x >> 4;
    const int    chunk = blockIdx.x & 15;
    const size_t base  = (size_t)b * DIM + chunk * 32;
    const float* __restrict__ ir = layer ? g_re : in_re;
    const float* __restrict__ ii = layer ? g_im : in_im;

#pragma unroll
    for (int j = 0; j < TILE / THREADS; j++) {
        int e = j * THREADS + t;
        size_t g = base + ((size_t)(e >> 5) << 9) + (e & 31);   // coalesced 128B groups
        sre[e] = ir[g];
        sim[e] = ii[g];
    }
    __syncthreads();

    // Rotations: wire w (0..8) -> h-bit q = 8-w. Pair stride 32<<q (bank-clean).
#pragma unroll
    for (int w = 0; w < 9; w++) {
        const int q = 8 - w;
        const float4 tr = g_trig[layer][w];
        const int mask = (1 << q) - 1;
#pragma unroll
        for (int j = 0; j < TILE / 2 / THREADS; j++) {
            int u  = j * THREADS + t;
            int lo = u & 31;
            int r  = u >> 5;
            int m0 = ((((r >> q) << (q + 1)) | (r & mask)) << 5) | lo;
            int m1 = m0 + (32 << q);
            rot_pair(sre, sim, m0, m1, tr.x, tr.y, tr.z, tr.w);
        }
        __syncthreads();
    }

    // CNOTs C(17->16)..C(10->9): control h-bit qc, target qc-1. Swap where qc=1.
#pragma unroll
    for (int qc = 8; qc >= 1; qc--) {
        const int qt = qc - 1;
        const int maskt = (1 << qt) - 1;
#pragma unroll
        for (int j = 0; j < TILE / 4 / THREADS; j++) {
            int u  = j * THREADS + t;
            int lo = u & 31;
            int r  = u >> 5;
            int m0 = ((((r >> qt) << (qt + 2)) | (1 << qc) | (r & maskt)) << 5) | lo;
            int m1 = m0 + (32 << qt);
            float a = sre[m0]; sre[m0] = sre[m1]; sre[m1] = a;
            float c = sim[m0]; sim[m0] = sim[m1]; sim[m1] = c;
        }
        __syncthreads();
    }

#pragma unroll
    for (int j = 0; j < TILE / THREADS; j++) {
        int e = j * THREADS + t;
        size_t g = base + ((size_t)(e >> 5) << 9) + (e & 31);
        g_re[g] = sre[e];
        g_im[g] = sim[e];
    }
}

// ---------------------------------------------------------------------------
// L pass: bits 0..8 (wires 9..17) + boundary CNOT with bit 9 as in-tile control.
// Tile = contiguous 2^14 amplitudes (bits 0..13 in tile, bits 14..17 = chunk).
__global__ __launch_bounds__(THREADS, 1)
void l_kernel(int layer, int last) {
    extern __shared__ float smem[];
    float* sre = smem;
    float* sim = smem + TILE;
    const int    t     = threadIdx.x;
    const int    b     = blockIdx.x >> 4;
    const int    chunk = blockIdx.x & 15;
    const size_t base  = (size_t)b * DIM + (size_t)chunk * TILE;

#pragma unroll
    for (int j = 0; j < TILE / THREADS; j++) {
        int e = j * THREADS + t;
        sre[e] = g_re[base + e];
        sim[e] = g_im[base + e];
    }
    __syncthreads();

    // Rotations: wire w (9..17) -> bit p = 17-w.
#pragma unroll
    for (int w = 9; w < 18; w++) {
        const int p = 17 - w;
        const float4 tr = g_trig[layer][w];
        const int mask = (1 << p) - 1;
#pragma unroll
        for (int j = 0; j < TILE / 2 / THREADS; j++) {
            int u  = j * THREADS + t;
            int m0 = ((u >> p) << (p + 1)) | (u & mask);
            int m1 = m0 + (1 << p);
            rot_pair(sre, sim, m0, m1, tr.x, tr.y, tr.z, tr.w);
        }
        __syncthreads();
    }

    // Boundary CNOT C(9->8): bit 9 = control (read-only), swap along bit 8 where set.
#pragma unroll
    for (int j = 0; j < TILE / 4 / THREADS; j++) {
        int u  = j * THREADS + t;
        int m0 = ((u >> 8) << 10) | (1 << 9) | (u & 255);
        int m1 = m0 + 256;
        float a = sre[m0]; sre[m0] = sre[m1]; sre[m1] = a;
        float c = sim[m0]; sim[m0] = sim[m1]; sim[m1] = c;
    }
    __syncthreads();

    // CNOTs C(8->7)..C(1->0).
#pragma unroll
    for (int p = 8; p >= 1; p--) {
        const int pt = p - 1;
        const int maskt = (1 << pt) - 1;
#pragma unroll
        for (int j = 0; j < TILE / 4 / THREADS; j++) {
            int u  = j * THREADS + t;
            int m0 = ((u >> pt) << (pt + 2)) | (1 << p) | (u & maskt);
            int m1 = m0 + (1 << pt);
            float a = sre[m0]; sre[m0] = sre[m1]; sre[m1] = a;
            float c = sim[m0]; sim[m0] = sim[m1]; sim[m1] = c;
        }
        __syncthreads();
    }

    if (!last) {
#pragma unroll
        for (int j = 0; j < TILE / THREADS; j++) {
            int e = j * THREADS + t;
            g_re[base + e] = sre[e];
            g_im[base + e] = sim[e];
        }
    } else {
        // Fused Z-expval partials: total prob + signed sums over in-tile bits 0..13.
        float acc[NPART];
#pragma unroll
        for (int i = 0; i < NPART; i++) acc[i] = 0.f;
#pragma unroll
        for (int j = 0; j < TILE / THREADS; j++) {
            int e = j * THREADS + t;
            float re = sre[e], im = sim[e];
            float pr = re * re + im * im;
            acc[14] += pr;
#pragma unroll
            for (int p = 0; p < 14; p++)
                acc[p] += ((e >> p) & 1) ? -pr : pr;
        }
#pragma unroll
        for (int i = 0; i < NPART; i++)
#pragma unroll
            for (int o = 16; o > 0; o >>= 1)
                acc[i] += __shfl_xor_sync(0xffffffffu, acc[i], o);
        __syncthreads();
        int lane = t & 31, warp = t >> 5;
        if (lane == 0) {
#pragma unroll
            for (int i = 0; i < NPART; i++) sre[warp * NPART + i] = acc[i];
        }
        __syncthreads();
        if (t < NPART) {
            float s = 0.f;
            for (int wp = 0; wp < THREADS / 32; wp++) s += sre[wp * NPART + t];
            g_part[((size_t)b * CHUNKS + chunk) * NPART + t] = s;
        }
    }
}

// ---------------------------------------------------------------------------
__global__ void head_kernel(const float* __restrict__ head_w,
                            const float* __restrict__ head_b,
                            float* __restrict__ out) {
    int b = threadIdx.x;
    if (b >= BATCH) return;
    float fw[NW];
#pragma unroll
    for (int w = 0; w < NW; w++) fw[w] = 0.f;
    for (int c = 0; c < CHUNKS; c++) {
        const float* pp = &g_part[((size_t)b * CHUNKS + c) * NPART];
        float sp = pp[14];
#pragma unroll
        for (int p = 0; p < 14; p++) fw[17 - p] += pp[p];        // in-tile bits
#pragma unroll
        for (int p = 14; p < 18; p++)                            // chunk bits
            fw[17 - p] += ((c >> (p - 14)) & 1) ? -sp : sp;
    }
    float o = head_b[0];
#pragma unroll
    for (int w = 0; w < NW; w++) o += fw[w] * head_w[w];
    out[b] = o;
}

// ---------------------------------------------------------------------------
extern "C" void kernel_launch(void* const* d_in, const int* in_sizes, int n_in,
                              void* d_out, int out_size) {
    const float* state_re = (const float*)d_in[0];
    const float* state_im = (const float*)d_in[1];
    const float* params   = (const float*)d_in[2];
    const float* head_w   = (const float*)d_in[3];
    const float* head_b   = (const float*)d_in[4];
    float* out = (float*)d_out;

    const size_t smem = 2 * TILE * sizeof(float);   // 128 KB
    cudaFuncSetAttribute(h_kernel, cudaFuncAttributeMaxDynamicSharedMemorySize, (int)smem);
    cudaFuncSetAttribute(l_kernel, cudaFuncAttributeMaxDynamicSharedMemorySize, (int)smem);

    prep_kernel<<<1, 64>>>(params);
    for (int l = 0; l < 3; l++) {
        h_kernel<<<BATCH * CHUNKS, THREADS, smem>>>(state_re, state_im, l);
        l_kernel<<<BATCH * CHUNKS, THREADS, smem>>>(l, l == 2);
    }
    head_kernel<<<1, BATCH>>>(head_w, head_b, out);
}

// round 3
// speedup vs baseline: 1.5370x; 1.5370x over previous
#include <cuda_runtime.h>

#define NW      18
#define NBITS   18
#define DIM     (1 << NBITS)
#define BATCH   64
#define TILE    16384          // 2^14 amplitudes staged per CTA (128 KB re+im)
#define THREADS 1024
#define CHUNKS  16             // tiles per batch element (DIM / TILE)
#define NPART   15             // 14 signed bit-sums + total prob

// Scratch state (128 MB) — __device__ globals per allocation rules.
__device__ float  g_re[(size_t)BATCH * DIM];
__device__ float  g_im[(size_t)BATCH * DIM];
__device__ float4 g_trig[3][NW];                       // cy, sy, cz, sz per (layer, wire)
__device__ float  g_part[BATCH * CHUNKS * NPART];      // expval partials

// ---------------------------------------------------------------------------
__global__ void prep_kernel(const float* __restrict__ params) {
    int t = threadIdx.x;
    if (t < 3 * NW) {
        int l = t / NW, w = t % NW;
        float cy, sy, cz, sz;
        sincosf(0.5f * params[l * 36 + w],       &sy, &cy);   // params[l,0,w]
        sincosf(0.5f * params[l * 36 + NW + w],  &sz, &cz);   // params[l,1,w]
        g_trig[l][w] = make_float4(cy, sy, cz, sz);
    }
}

// Fused RY then RZ on an amplitude pair (m0: bit=0, m1: bit=1).
__device__ __forceinline__ void rot_pair(float* sre, float* sim, int m0, int m1,
                                         float cy, float sy, float cz, float sz) {
    float ar = sre[m0], ai = sim[m0], br = sre[m1], bi = sim[m1];
    float nar = cy * ar - sy * br, nai = cy * ai - sy * bi;   // RY
    float nbr = sy * ar + cy * br, nbi = sy * ai + cy * bi;
    sre[m0] = nar * cz + nai * sz;                            // RZ: * exp(-i th/2)
    sim[m0] = nai * cz - nar * sz;
    sre[m1] = nbr * cz - nbi * sz;                            // RZ: * exp(+i th/2)
    sim[m1] = nbi * cz + nbr * sz;
}

// ---------------------------------------------------------------------------
// H pass: bits 9..17 (wires 0..8). Tile = all 512 high combos x 32 contiguous lows.
// SMEM index m = h*32 + lo, global = b*DIM + h*512 + chunk*32 + lo.
__global__ __launch_bounds__(THREADS, 1)
void h_kernel(const float* __restrict__ in_re, const float* __restrict__ in_im, int layer) {
    extern __shared__ float smem[];
    float* sre = smem;
    float* sim = smem + TILE;
    const int    t     = threadIdx.x;
    const int    b     = blockIdx.x >> 4;
    const int    chunk = blockIdx.x & 15;
    const size_t base  = (size_t)b * DIM + chunk * 32;
    const float* __restrict__ ir = layer ? g_re : in_re;
    const float* __restrict__ ii = layer ? g_im : in_im;

#pragma unroll
    for (int j = 0; j < TILE / THREADS; j++) {
        int e = j * THREADS + t;
        size_t g = base + ((size_t)(e >> 5) << 9) + (e & 31);   // coalesced 128B groups
        sre[e] = ir[g];
        sim[e] = ii[g];
    }
    __syncthreads();

    // Rotations: wire w (0..8) -> h-bit q = 8-w. Pair stride 32<<q (bank-clean).
#pragma unroll
    for (int w = 0; w < 9; w++) {
        const int q = 8 - w;
        const float4 tr = g_trig[layer][w];
        const int mask = (1 << q) - 1;
#pragma unroll
        for (int j = 0; j < TILE / 2 / THREADS; j++) {
            int u  = j * THREADS + t;
            int lo = u & 31;
            int r  = u >> 5;
            int m0 = ((((r >> q) << (q + 1)) | (r & mask)) << 5) | lo;
            int m1 = m0 + (32 << q);
            rot_pair(sre, sim, m0, m1, tr.x, tr.y, tr.z, tr.w);
        }
        __syncthreads();
    }

    // CNOTs C(17->16)..C(10->9): control h-bit qc, target qc-1. Swap where qc=1.
#pragma unroll
    for (int qc = 8; qc >= 1; qc--) {
        const int qt = qc - 1;
        const int maskt = (1 << qt) - 1;
#pragma unroll
        for (int j = 0; j < TILE / 4 / THREADS; j++) {
            int u  = j * THREADS + t;
            int lo = u & 31;
            int r  = u >> 5;
            int m0 = ((((r >> qt) << (qt + 2)) | (1 << qc) | (r & maskt)) << 5) | lo;
            int m1 = m0 + (32 << qt);
            float a = sre[m0]; sre[m0] = sre[m1]; sre[m1] = a;
            float c = sim[m0]; sim[m0] = sim[m1]; sim[m1] = c;
        }
        __syncthreads();
    }

#pragma unroll
    for (int j = 0; j < TILE / THREADS; j++) {
        int e = j * THREADS + t;
        size_t g = base + ((size_t)(e >> 5) << 9) + (e & 31);
        g_re[g] = sre[e];
        g_im[g] = sim[e];
    }
}

// ---------------------------------------------------------------------------
// L pass: bits 0..8 (wires 9..17) + boundary CNOT with bit 9 as in-tile control.
// Tile = contiguous 2^14 amplitudes (bits 0..13 in tile, bits 14..17 = chunk).
__global__ __launch_bounds__(THREADS, 1)
void l_kernel(int layer, int last) {
    extern __shared__ float smem[];
    float* sre = smem;
    float* sim = smem + TILE;
    const int    t     = threadIdx.x;
    const int    b     = blockIdx.x >> 4;
    const int    chunk = blockIdx.x & 15;
    const size_t base  = (size_t)b * DIM + (size_t)chunk * TILE;

#pragma unroll
    for (int j = 0; j < TILE / THREADS; j++) {
        int e = j * THREADS + t;
        sre[e] = g_re[base + e];
        sim[e] = g_im[base + e];
    }
    __syncthreads();

    // Rotations: wire w (9..17) -> bit p = 17-w.
#pragma unroll
    for (int w = 9; w < 18; w++) {
        const int p = 17 - w;
        const float4 tr = g_trig[layer][w];
        const int mask = (1 << p) - 1;
#pragma unroll
        for (int j = 0; j < TILE / 2 / THREADS; j++) {
            int u  = j * THREADS + t;
            int m0 = ((u >> p) << (p + 1)) | (u & mask);
            int m1 = m0 + (1 << p);
            rot_pair(sre, sim, m0, m1, tr.x, tr.y, tr.z, tr.w);
        }
        __syncthreads();
    }

    // Boundary CNOT C(9->8): bit 9 = control (read-only), swap along bit 8 where set.
#pragma unroll
    for (int j = 0; j < TILE / 4 / THREADS; j++) {
        int u  = j * THREADS + t;
        int m0 = ((u >> 8) << 10) | (1 << 9) | (u & 255);
        int m1 = m0 + 256;
        float a = sre[m0]; sre[m0] = sre[m1]; sre[m1] = a;
        float c = sim[m0]; sim[m0] = sim[m1]; sim[m1] = c;
    }
    __syncthreads();

    // CNOTs C(8->7)..C(1->0).
#pragma unroll
    for (int p = 8; p >= 1; p--) {
        const int pt = p - 1;
        const int maskt = (1 << pt) - 1;
#pragma unroll
        for (int j = 0; j < TILE / 4 / THREADS; j++) {
            int u  = j * THREADS + t;
            int m0 = ((u >> pt) << (pt + 2)) | (1 << p) | (u & maskt);
            int m1 = m0 + (1 << pt);
            float a = sre[m0]; sre[m0] = sre[m1]; sre[m1] = a;
            float c = sim[m0]; sim[m0] = sim[m1]; sim[m1] = c;
        }
        __syncthreads();
    }

    if (!last) {
#pragma unroll
        for (int j = 0; j < TILE / THREADS; j++) {
            int e = j * THREADS + t;
            g_re[base + e] = sre[e];
            g_im[base + e] = sim[e];
        }
    } else {
        // Fused Z-expval partials: total prob + signed sums over in-tile bits 0..13.
        float acc[NPART];
#pragma unroll
        for (int i = 0; i < NPART; i++) acc[i] = 0.f;
#pragma unroll
        for (int j = 0; j < TILE / THREADS; j++) {
            int e = j * THREADS + t;
            float re = sre[e], im = sim[e];
            float pr = re * re + im * im;
            acc[14] += pr;
#pragma unroll
            for (int p = 0; p < 14; p++)
                acc[p] += ((e >> p) & 1) ? -pr : pr;
        }
#pragma unroll
        for (int i = 0; i < NPART; i++)
#pragma unroll
            for (int o = 16; o > 0; o >>= 1)
                acc[i] += __shfl_xor_sync(0xffffffffu, acc[i], o);
        __syncthreads();
        int lane = t & 31, warp = t >> 5;
        if (lane == 0) {
#pragma unroll
            for (int i = 0; i < NPART; i++) sre[warp * NPART + i] = acc[i];
        }
        __syncthreads();
        if (t < NPART) {
            float s = 0.f;
            for (int wp = 0; wp < THREADS / 32; wp++) s += sre[wp * NPART + t];
            g_part[((size_t)b * CHUNKS + chunk) * NPART + t] = s;
        }
    }
}

// ---------------------------------------------------------------------------
__global__ void head_kernel(const float* __restrict__ head_w,
                            const float* __restrict__ head_b,
                            float* __restrict__ out) {
    int b = threadIdx.x;
    if (b >= BATCH) return;
    float fw[NW];
#pragma unroll
    for (int w = 0; w < NW; w++) fw[w] = 0.f;
    for (int c = 0; c < CHUNKS; c++) {
        const float* pp = &g_part[((size_t)b * CHUNKS + c) * NPART];
        float sp = pp[14];
#pragma unroll
        for (int p = 0; p < 14; p++) fw[17 - p] += pp[p];        // in-tile bits
#pragma unroll
        for (int p = 14; p < 18; p++)                            // chunk bits
            fw[17 - p] += ((c >> (p - 14)) & 1) ? -sp : sp;
    }
    float o = head_b[0];
#pragma unroll
    for (int w = 0; w < NW; w++) o += fw[w] * head_w[w];
    out[b] = o;
}

// ---------------------------------------------------------------------------
extern "C" void kernel_launch(void* const* d_in, const int* in_sizes, int n_in,
                              void* d_out, int out_size) {
    const float* state_re = (const float*)d_in[0];
    const float* state_im = (const float*)d_in[1];
    const float* params   = (const float*)d_in[2];
    const float* head_w   = (const float*)d_in[3];
    const float* head_b   = (const float*)d_in[4];
    float* out = (float*)d_out;

    const size_t smem = 2 * TILE * sizeof(float);   // 128 KB
    cudaFuncSetAttribute(h_kernel, cudaFuncAttributeMaxDynamicSharedMemorySize, (int)smem);
    cudaFuncSetAttribute(l_kernel, cudaFuncAttributeMaxDynamicSharedMemorySize, (int)smem);

    prep_kernel<<<1, 64>>>(params);
    for (int l = 0; l < 3; l++) {
        h_kernel<<<BATCH * CHUNKS, THREADS, smem>>>(state_re, state_im, l);
        l_kernel<<<BATCH * CHUNKS, THREADS, smem>>>(l, l == 2);
    }
    head_kernel<<<1, BATCH>>>(head_w, head_b, out);
}

// round 5
// speedup vs baseline: 3.4508x; 2.2451x over previous
#include <cuda_runtime.h>

#define NW      18
#define DIM     (1 << 18)
#define BATCH   64
#define THREADS 512
#define TILE    8192           // amplitudes per CTA (float2 -> 64 KB smem)
#define NACC    14             // 13 masked sums (bits 0..12) + total prob

// Ping-pong state buffers (128 MB each) — __device__ globals per allocation rules.
// h_kernel: reads inputs (layer 0) or g_b, writes g_a.
// l_kernel: reads g_a, writes g_b (or fused exp-val on last layer).
__device__ float2 g_a[(size_t)BATCH * DIM];
__device__ float2 g_b[(size_t)BATCH * DIM];
__device__ float4 g_trig[3][NW];                  // cy, sy, cz, sz
__device__ float  g_part[BATCH * 32 * NACC];

// ---------------------------------------------------------------------------
__global__ void prep_kernel(const float* __restrict__ params) {
    int t = threadIdx.x;
    if (t < 3 * NW) {
        int l = t / NW, w = t % NW;
        float cy, sy, cz, sz;
        sincosf(0.5f * params[l * 36 + w],      &sy, &cy);   // params[l,0,w]
        sincosf(0.5f * params[l * 36 + NW + w], &sz, &cz);   // params[l,1,w]
        g_trig[l][w] = make_float4(cy, sy, cz, sz);
    }
}

// RY then RZ on a register pair (A: bit=0 element, B: bit=1 element).
__device__ __forceinline__ void rp2(float2& A, float2& B, float4 T) {
    float nar = T.x * A.x - T.y * B.x;
    float nai = T.x * A.y - T.y * B.y;
    float nbr = T.y * A.x + T.x * B.x;
    float nbi = T.y * A.y + T.x * B.y;
    A.x = nar * T.z + nai * T.w;
    A.y = nai * T.z - nar * T.w;
    B.x = nbr * T.z - nbi * T.w;
    B.y = nbi * T.z + nbr * T.w;
}

// RY+RZ where the pair partner lives in lane ^ d.
__device__ __forceinline__ void shrot(float2& v, float4 T, float sgn, float zs, int d) {
    float orr = __shfl_xor_sync(0xffffffffu, v.x, d);
    float ori = __shfl_xor_sync(0xffffffffu, v.y, d);
    float nr = T.x * v.x + sgn * orr;
    float ni = T.x * v.y + sgn * ori;
    v.x = nr * T.z + zs * ni;
    v.y = ni * T.z - zs * nr;
}

__device__ __forceinline__ void rot8(float2 (&v)[8], float4 T0, float4 T1, float4 T2) {
    rp2(v[0], v[1], T0); rp2(v[2], v[3], T0); rp2(v[4], v[5], T0); rp2(v[6], v[7], T0);
    rp2(v[0], v[2], T1); rp2(v[1], v[3], T1); rp2(v[4], v[6], T1); rp2(v[5], v[7], T1);
    rp2(v[0], v[4], T2); rp2(v[1], v[5], T2); rp2(v[2], v[6], T2); rp2(v[3], v[7], T2);
}

// ---------------------------------------------------------------------------
// H kernel: rotations on global bits 10..17 (wires 0..7).
// Tile bits {0..4} u {10..17}; chunk = bits 5..9. Read folds previous layer's
// low CNOT chain segment (targets 0..11). One swizzled SMEM transpose each way.
__global__ __launch_bounds__(THREADS, 2)
void h_kernel(const float* __restrict__ in_re, const float* __restrict__ in_im, int layer) {
    extern __shared__ float2 sm[];
    const int t = threadIdx.x, lane = t & 31, wrp = t >> 5;
    const int b = blockIdx.x >> 5, chunk = blockIdx.x & 31;
    const size_t base = (size_t)b * DIM;

    if (layer == 0) {
#pragma unroll
        for (int i = 0; i < 16; i++) {
            int e = i * THREADS + t;
            int a = (e & 31) | (chunk << 5) | ((e >> 5) << 10);
            sm[e ^ ((e >> 5) & 31)] = make_float2(in_re[base + a], in_im[base + a]);
        }
    } else {
#pragma unroll
        for (int i = 0; i < 16; i++) {
            int e = i * THREADS + t;
            int a = (e & 31) | (chunk << 5) | ((e >> 5) << 10);
            a ^= (a >> 1) & 0x0FFF;                 // fold: prior layer chain C(12..1)
            sm[e ^ ((e >> 5) & 31)] = g_b[base + a];
        }
    }
    __syncthreads();

    // e-bits {5..9} = lane -> global bits 10..14 (wires 7..3) via shfl;
    // e-bits {10..12} = regs -> global bits 15..17 (wires 2..0).
#pragma unroll
    for (int j = 0; j < 2; j++) {
        const int lo = wrp | (j << 4);
        float2 v[8];
#pragma unroll
        for (int r = 0; r < 8; r++)
            v[r] = sm[(lo ^ lane) | (lane << 5) | (r << 10)];
#pragma unroll
        for (int q = 0; q < 5; q++) {
            float4 T = g_trig[layer][7 - q];
            int bit = (lane >> q) & 1;
            float sgn = bit ? T.y : -T.y;
            float zs  = bit ? -T.w : T.w;
#pragma unroll
            for (int r = 0; r < 8; r++) shrot(v[r], T, sgn, zs, 1 << q);
        }
        rot8(v, g_trig[layer][2], g_trig[layer][1], g_trig[layer][0]);
#pragma unroll
        for (int r = 0; r < 8; r++)
            sm[(lo ^ lane) | (lane << 5) | (r << 10)] = v[r];
    }
    __syncthreads();

#pragma unroll
    for (int i = 0; i < 16; i++) {
        int e = i * THREADS + t;
        int a = (e & 31) | (chunk << 5) | ((e >> 5) << 10);
        g_a[base + a] = sm[e ^ ((e >> 5) & 31)];
    }
}

// ---------------------------------------------------------------------------
// L kernel: rotations on global bits 0..9 (wires 17..8).
// Tile = contiguous bits 0..12; chunk = bits 13..17. Read folds this layer's
// high CNOT chain segment (targets 12..16). Phase 1: bits 0..4 via shfl,
// 5..7 in regs. One SMEM exchange. Phase 2: bits 8,9 in regs, then store
// (or fused exp-val with suffix-parity sign masks on the last layer).
__global__ __launch_bounds__(THREADS, 2)
void l_kernel(int layer, int last) {
    extern __shared__ float2 sm[];
    const int t = threadIdx.x, lane = t & 31, wrp = t >> 5;
    const int b = blockIdx.x >> 5, chunk = blockIdx.x & 31;
    const size_t base = (size_t)b * DIM;

#pragma unroll
    for (int j = 0; j < 2; j++) {
        const int hi = (wrp | (j << 4)) << 8;
        float2 v[8];
#pragma unroll
        for (int r = 0; r < 8; r++) {
            int a = (chunk << 13) | lane | (r << 5) | hi;
            a ^= (a >> 1) & 0x1F000;                // fold: this layer chain C(17..13)
            v[r] = g_a[base + a];
        }
#pragma unroll
        for (int q = 0; q < 5; q++) {
            float4 T = g_trig[layer][17 - q];
            int bit = (lane >> q) & 1;
            float sgn = bit ? T.y : -T.y;
            float zs  = bit ? -T.w : T.w;
#pragma unroll
            for (int r = 0; r < 8; r++) shrot(v[r], T, sgn, zs, 1 << q);
        }
        rot8(v, g_trig[layer][12], g_trig[layer][11], g_trig[layer][10]);
#pragma unroll
        for (int r = 0; r < 8; r++)
            sm[lane | (r << 5) | hi] = v[r];
    }
    __syncthreads();

    float acc[NACC];
    if (last)
#pragma unroll
        for (int i = 0; i < NACC; i++) acc[i] = 0.f;

    const float4 T8 = g_trig[layer][9];   // global bit 8 -> wire 9
    const float4 T9 = g_trig[layer][8];   // global bit 9 -> wire 8
#pragma unroll
    for (int u = 0; u < 4; u++) {
        const int ex = ((wrp & 7) << 5) | (((wrp >> 3) | (u << 1)) << 10);
        float2 v[4];
#pragma unroll
        for (int r = 0; r < 4; r++)
            v[r] = sm[lane | ex | ((r & 1) << 8) | ((r >> 1) << 9)];
        rp2(v[0], v[1], T8); rp2(v[2], v[3], T8);
        rp2(v[0], v[2], T9); rp2(v[1], v[3], T9);
        if (!last) {
#pragma unroll
            for (int r = 0; r < 4; r++) {
                int e = lane | ex | ((r & 1) << 8) | ((r >> 1) << 9);
                g_b[base + (size_t)((chunk << 13) | e)] = v[r];
            }
        } else {
#pragma unroll
            for (int r = 0; r < 4; r++) {
                int e = lane | ex | ((r & 1) << 8) | ((r >> 1) << 9);
                float pr = v[r].x * v[r].x + v[r].y * v[r].y;
                int p = e;                            // suffix parity: bit k = XOR e[k..12]
                p ^= p >> 1; p ^= p >> 2; p ^= p >> 4; p ^= p >> 8;
#pragma unroll
                for (int k = 0; k < 13; k++)
                    acc[k] += ((p >> k) & 1) ? -pr : pr;
                acc[13] += pr;
            }
        }
    }

    if (last) {
#pragma unroll
        for (int i = 0; i < NACC; i++)
#pragma unroll
            for (int o = 16; o > 0; o >>= 1)
                acc[i] += __shfl_xor_sync(0xffffffffu, acc[i], o);
        __syncthreads();
        float* red = (float*)sm;
        if (lane == 0)
#pragma unroll
            for (int i = 0; i < NACC; i++) red[wrp * NACC + i] = acc[i];
        __syncthreads();
        if (t < NACC) {
            float s = 0.f;
            for (int w2 = 0; w2 < 16; w2++) s += red[w2 * NACC + t];
            g_part[(b * 32 + chunk) * NACC + t] = s;
        }
    }
}

// ---------------------------------------------------------------------------
__global__ void head_kernel(const float* __restrict__ head_w,
                            const float* __restrict__ head_b,
                            float* __restrict__ out) {
    int b = threadIdx.x;
    if (b >= BATCH) return;
    float fw[NW];
#pragma unroll
    for (int w = 0; w < NW; w++) fw[w] = 0.f;
    for (int c = 0; c < 32; c++) {
        const float* pp = &g_part[(b * 32 + c) * NACC];
#pragma unroll
        for (int k = 0; k < 13; k++) fw[17 - k] += pp[k];    // in-tile masks
        float sp = pp[13];
#pragma unroll
        for (int k = 13; k < 18; k++)                        // chunk-bit signs
            fw[17 - k] += ((c >> (k - 13)) & 1) ? -sp : sp;
    }
    float o = head_b[0];
#pragma unroll
    for (int w = 0; w < NW; w++) o += fw[w] * head_w[w];
    out[b] = o;
}

// ---------------------------------------------------------------------------
extern "C" void kernel_launch(void* const* d_in, const int* in_sizes, int n_in,
                              void* d_out, int out_size) {
    const float* state_re = (const float*)d_in[0];
    const float* state_im = (const float*)d_in[1];
    const float* params   = (const float*)d_in[2];
    const float* head_w   = (const float*)d_in[3];
    const float* head_b   = (const float*)d_in[4];
    float* out = (float*)d_out;

    const int smem = TILE * sizeof(float2);   // 64 KB
    cudaFuncSetAttribute(h_kernel, cudaFuncAttributeMaxDynamicSharedMemorySize, smem);
    cudaFuncSetAttribute(l_kernel, cudaFuncAttributeMaxDynamicSharedMemorySize, smem);

    prep_kernel<<<1, 64>>>(params);
    for (int l = 0; l < 3; l++) {
        h_kernel<<<BATCH * 32, THREADS, smem>>>(state_re, state_im, l);
        l_kernel<<<BATCH * 32, THREADS, smem>>>(l, l == 2);
    }
    head_kernel<<<1, BATCH>>>(head_w, head_b, out);
}

// round 6
// speedup vs baseline: 4.0956x; 1.1869x over previous
#include <cuda_runtime.h>

#define NW      18
#define DIM     (1 << 18)
#define BATCH   64
#define THREADS 512
#define TILE    8192           // amplitudes per CTA (u64 re/im pair -> 64 KB smem)
#define NACC    14             // 13 masked sums (bits 0..12) + total prob

typedef unsigned long long u64;

// Ping-pong state buffers (128 MB each). h: reads input/g_b, writes g_a.
// l: reads g_a, writes g_b (or fused exp-val on last layer).
__device__ u64    g_a[(size_t)BATCH * DIM];
__device__ u64    g_b[(size_t)BATCH * DIM];
__device__ float4 g_half[3][NW];   // cy, sy, cos(th_z/2), sin(th_z/2)
__device__ float2 g_full[3][NW];   // cos(th_z),  sin(th_z)
__device__ float  g_part[BATCH * 32 * NACC];

// ---- packed f32x2 helpers ---------------------------------------------------
static __device__ __forceinline__ u64 pk2(float x, float y) {
    u64 r; asm("mov.b64 %0,{%1,%2};" : "=l"(r) : "f"(x), "f"(y)); return r;
}
static __device__ __forceinline__ void up2(u64 a, float& x, float& y) {
    asm("mov.b64 {%0,%1},%2;" : "=f"(x), "=f"(y) : "l"(a));
}
static __device__ __forceinline__ u64 fma2_(u64 a, u64 b, u64 c) {
    u64 r; asm("fma.rn.f32x2 %0,%1,%2,%3;" : "=l"(r) : "l"(a), "l"(b), "l"(c)); return r;
}
static __device__ __forceinline__ u64 mul2_(u64 a, u64 b) {
    u64 r; asm("mul.rn.f32x2 %0,%1,%2;" : "=l"(r) : "l"(a), "l"(b)); return r;
}

// ---------------------------------------------------------------------------
__global__ void prep_kernel(const float* __restrict__ params) {
    int t = threadIdx.x;
    if (t < 3 * NW) {
        int l = t / NW, w = t % NW;
        float cy, sy, czh, szh, czf, szf;
        sincosf(0.5f * params[l * 36 + w],      &sy,  &cy);    // params[l,0,w]
        sincosf(0.5f * params[l * 36 + NW + w], &szh, &czh);   // params[l,1,w] half
        sincosf(params[l * 36 + NW + w],        &szf, &czf);   // full angle
        g_half[l][w] = make_float4(cy, sy, czh, szh);
        g_full[l][w] = make_float2(czf, szf);
    }
}

// Rotation coefficients for the register-pair path (RY half-angle + RZ full
// angle applied to the bit=0 amplitude only; global phase e^{+i th/2} dropped —
// valid because the output depends only on |amp|^2).
struct RC { u64 cy2, sy2, msy2; float cf, sf; };
static __device__ __forceinline__ RC mkrc(int l, int w) {
    float4 H = g_half[l][w]; float2 F = g_full[l][w];
    RC r;
    r.cy2  = pk2(H.x, H.x);
    r.sy2  = pk2(H.y, H.y);
    r.msy2 = pk2(-H.y, -H.y);
    r.cf = F.x; r.sf = F.y;
    return r;
}

// RY then RZ(global-phase-reduced) on a register pair (A: bit=0, B: bit=1).
static __device__ __forceinline__ void rp2p(u64& A, u64& B, const RC& r) {
    u64 nA = fma2_(r.cy2, A, mul2_(r.msy2, B));   // A' = cy*A - sy*B
    u64 nB = fma2_(r.sy2, A, mul2_(r.cy2,  B));   // B' = sy*A + cy*B
    float ax, ay; up2(nA, ax, ay);
    A = pk2(fmaf(ay, r.sf, ax * r.cf),            // A'' = A' * e^{-i th}
            fmaf(-ax, r.sf, ay * r.cf));
    B = nB;
}

// RY+RZ(+-half-angle) where the pair partner lives in lane ^ d.
static __device__ __forceinline__ void shrotp(u64& v, u64 cy2, u64 sgn2,
                                              float cz, float zs, int d) {
    float vx, vy; up2(v, vx, vy);
    float ox = __shfl_xor_sync(0xffffffffu, vx, d);
    float oy = __shfl_xor_sync(0xffffffffu, vy, d);
    u64 n = fma2_(cy2, v, mul2_(sgn2, pk2(ox, oy)));
    float nx, ny; up2(n, nx, ny);
    v = pk2(fmaf(zs, ny, nx * cz), fmaf(-zs, nx, ny * cz));
}

// Three register-bit rotations over v[8]: pairing strides 1, 2, 4.
static __device__ __forceinline__ void rot8p(u64 (&v)[8], int l, int wa, int wb, int wc) {
    { RC r = mkrc(l, wa); rp2p(v[0],v[1],r); rp2p(v[2],v[3],r); rp2p(v[4],v[5],r); rp2p(v[6],v[7],r); }
    { RC r = mkrc(l, wb); rp2p(v[0],v[2],r); rp2p(v[1],v[3],r); rp2p(v[4],v[6],r); rp2p(v[5],v[7],r); }
    { RC r = mkrc(l, wc); rp2p(v[0],v[4],r); rp2p(v[1],v[5],r); rp2p(v[2],v[6],r); rp2p(v[3],v[7],r); }
}

// ---------------------------------------------------------------------------
// H kernel: rotations on global bits 10..17 (wires 0..7).
// Tile bits {0..4} u {10..17}; chunk = bits 5..9. Read folds prior layer's
// low CNOT chain segment (targets 0..11). One swizzled SMEM transpose each way.
__global__ __launch_bounds__(THREADS, 2)
void h_kernel(const float* __restrict__ in_re, const float* __restrict__ in_im, int layer) {
    extern __shared__ u64 sm[];
    const int t = threadIdx.x, lane = t & 31, wrp = t >> 5;
    const int b = blockIdx.x >> 5, chunk = blockIdx.x & 31;
    const size_t base = (size_t)b * DIM;

    if (layer == 0) {
#pragma unroll
        for (int i = 0; i < 16; i++) {
            int e = i * THREADS + t;
            int a = (e & 31) | (chunk << 5) | ((e >> 5) << 10);
            sm[e ^ ((e >> 5) & 31)] = pk2(in_re[base + a], in_im[base + a]);
        }
    } else {
#pragma unroll
        for (int i = 0; i < 16; i++) {
            int e = i * THREADS + t;
            int a = (e & 31) | (chunk << 5) | ((e >> 5) << 10);
            a ^= (a >> 1) & 0x0FFF;                 // fold: prior layer chain C(12..1)
            sm[e ^ ((e >> 5) & 31)] = g_b[base + a];
        }
    }
    __syncthreads();

    // lane = global bits 10..14 (wires 7..3) via shfl; regs = bits 15..17 (wires 2..0).
#pragma unroll
    for (int j = 0; j < 2; j++) {
        const int lo = wrp | (j << 4);
        u64 v[8];
#pragma unroll
        for (int r = 0; r < 8; r++)
            v[r] = sm[(lo ^ lane) | (lane << 5) | (r << 10)];
#pragma unroll
        for (int q = 0; q < 5; q++) {
            float4 T = g_half[layer][7 - q];
            int bit = (lane >> q) & 1;
            float sgn = bit ? T.y : -T.y;
            float zs  = bit ? -T.w : T.w;
            u64 cy2 = pk2(T.x, T.x), sgn2 = pk2(sgn, sgn);
#pragma unroll
            for (int r = 0; r < 8; r++) shrotp(v[r], cy2, sgn2, T.z, zs, 1 << q);
        }
        rot8p(v, layer, 2, 1, 0);
#pragma unroll
        for (int r = 0; r < 8; r++)
            sm[(lo ^ lane) | (lane << 5) | (r << 10)] = v[r];
    }
    __syncthreads();

#pragma unroll
    for (int i = 0; i < 16; i++) {
        int e = i * THREADS + t;
        int a = (e & 31) | (chunk << 5) | ((e >> 5) << 10);
        g_a[base + a] = sm[e ^ ((e >> 5) & 31)];
    }
}

// ---------------------------------------------------------------------------
// L kernel: rotations on global bits 0..9 (wires 17..8).
// Tile = contiguous bits 0..12; chunk = bits 13..17. Read folds this layer's
// high CNOT chain segment (targets 12..16). Phase 1: bits 0..4 via shfl,
// 5..7 in regs. One SMEM exchange. Phase 2: bits 8,9 in regs, then store
// (or fused exp-val with suffix-parity sign masks on the last layer).
__global__ __launch_bounds__(THREADS, 2)
void l_kernel(int layer, int last) {
    extern __shared__ u64 sm[];
    const int t = threadIdx.x, lane = t & 31, wrp = t >> 5;
    const int b = blockIdx.x >> 5, chunk = blockIdx.x & 31;
    const size_t base = (size_t)b * DIM;

#pragma unroll
    for (int j = 0; j < 2; j++) {
        const int hi = (wrp | (j << 4)) << 8;
        u64 v[8];
#pragma unroll
        for (int r = 0; r < 8; r++) {
            int a = (chunk << 13) | lane | (r << 5) | hi;
            a ^= (a >> 1) & 0x1F000;                // fold: this layer chain C(17..13)
            v[r] = g_a[base + a];
        }
#pragma unroll
        for (int q = 0; q < 5; q++) {
            float4 T = g_half[layer][17 - q];
            int bit = (lane >> q) & 1;
            float sgn = bit ? T.y : -T.y;
            float zs  = bit ? -T.w : T.w;
            u64 cy2 = pk2(T.x, T.x), sgn2 = pk2(sgn, sgn);
#pragma unroll
            for (int r = 0; r < 8; r++) shrotp(v[r], cy2, sgn2, T.z, zs, 1 << q);
        }
        rot8p(v, layer, 12, 11, 10);
#pragma unroll
        for (int r = 0; r < 8; r++)
            sm[lane | (r << 5) | hi] = v[r];
    }
    __syncthreads();

    float acc[NACC];
    if (last)
#pragma unroll
        for (int i = 0; i < NACC; i++) acc[i] = 0.f;

    const RC rcb8 = mkrc(layer, 9);   // global bit 8 -> wire 9
    const RC rcb9 = mkrc(layer, 8);   // global bit 9 -> wire 8
#pragma unroll
    for (int u = 0; u < 4; u++) {
        const int ex = ((wrp & 7) << 5) | (((wrp >> 3) | (u << 1)) << 10);
        u64 v[4];
#pragma unroll
        for (int r = 0; r < 4; r++)
            v[r] = sm[lane | ex | ((r & 1) << 8) | ((r >> 1) << 9)];
        rp2p(v[0], v[1], rcb8); rp2p(v[2], v[3], rcb8);
        rp2p(v[0], v[2], rcb9); rp2p(v[1], v[3], rcb9);
        if (!last) {
#pragma unroll
            for (int r = 0; r < 4; r++) {
                int e = lane | ex | ((r & 1) << 8) | ((r >> 1) << 9);
                g_b[base + (size_t)((chunk << 13) | e)] = v[r];
            }
        } else {
#pragma unroll
            for (int r = 0; r < 4; r++) {
                int e = lane | ex | ((r & 1) << 8) | ((r >> 1) << 9);
                float vx, vy; up2(v[r], vx, vy);
                float pr = vx * vx + vy * vy;
                float prn = -pr;
                int p = e;                            // suffix parity: bit k = XOR e[k..12]
                p ^= p >> 1; p ^= p >> 2; p ^= p >> 4; p ^= p >> 8;
#pragma unroll
                for (int k = 0; k < 13; k++)
                    acc[k] += ((p >> k) & 1) ? prn : pr;
                acc[13] += pr;
            }
        }
    }

    if (last) {
#pragma unroll
        for (int i = 0; i < NACC; i++)
#pragma unroll
            for (int o = 16; o > 0; o >>= 1)
                acc[i] += __shfl_xor_sync(0xffffffffu, acc[i], o);
        __syncthreads();
        float* red = (float*)sm;
        if (lane == 0)
#pragma unroll
            for (int i = 0; i < NACC; i++) red[wrp * NACC + i] = acc[i];
        __syncthreads();
        if (t < NACC) {
            float s = 0.f;
            for (int w2 = 0; w2 < 16; w2++) s += red[w2 * NACC + t];
            g_part[(b * 32 + chunk) * NACC + t] = s;
        }
    }
}

// ---------------------------------------------------------------------------
__global__ void head_kernel(const float* __restrict__ head_w,
                            const float* __restrict__ head_b,
                            float* __restrict__ out) {
    int b = threadIdx.x;
    if (b >= BATCH) return;
    float fw[NW];
#pragma unroll
    for (int w = 0; w < NW; w++) fw[w] = 0.f;
    for (int c = 0; c < 32; c++) {
        const float* pp = &g_part[(b * 32 + c) * NACC];
#pragma unroll
        for (int k = 0; k < 13; k++) fw[17 - k] += pp[k];    // in-tile masks
        float sp = pp[13];
#pragma unroll
        for (int k = 13; k < 18; k++)                        // chunk-bit signs
            fw[17 - k] += ((c >> (k - 13)) & 1) ? -sp : sp;
    }
    float o = head_b[0];
#pragma unroll
    for (int w = 0; w < NW; w++) o += fw[w] * head_w[w];
    out[b] = o;
}

// ---------------------------------------------------------------------------
extern "C" void kernel_launch(void* const* d_in, const int* in_sizes, int n_in,
                              void* d_out, int out_size) {
    const float* state_re = (const float*)d_in[0];
    const float* state_im = (const float*)d_in[1];
    const float* params   = (const float*)d_in[2];
    const float* head_w   = (const float*)d_in[3];
    const float* head_b   = (const float*)d_in[4];
    float* out = (float*)d_out;

    const int smem = TILE * sizeof(u64);   // 64 KB
    cudaFuncSetAttribute(h_kernel, cudaFuncAttributeMaxDynamicSharedMemorySize, smem);
    cudaFuncSetAttribute(l_kernel, cudaFuncAttributeMaxDynamicSharedMemorySize, smem);

    prep_kernel<<<1, 64>>>(params);
    for (int l = 0; l < 3; l++) {
        h_kernel<<<BATCH * 32, THREADS, smem>>>(state_re, state_im, l);
        l_kernel<<<BATCH * 32, THREADS, smem>>>(l, l == 2);
    }
    head_kernel<<<1, BATCH>>>(head_w, head_b, out);
}